// round 16
// baseline (speedup 1.0000x reference)
#include <cuda_runtime.h>
#include <cstdint>

// CIC deposition: 10M particles -> 256^3 float grid.
// Round 16: R14 deposit (4-lane groups: lane (h,s) takes x-half h, z-block s;
// 2 RED instr/particle, ~3.12 effective sector-RMWs/particle) with B+flags
// packed into one shuffle. Overhead fused: single depermute kernel loads
// contiguous scratch tiles coalesced (float4), writes coalesced zeros back
// (restores scratch-zero invariant for graph replays -> no zero kernel),
// transposes through SMEM, streams coalesced float4 rows to d_out.

static constexpr float GMINF = -10.0f;
static constexpr float DXF   = (float)(20.0 / 255.0);

static constexpr size_t NBLK = 128u * 128u * 128u;       // 2,097,152 blocks
__device__ __align__(32) float g_scratch[NBLK * 8];      // 64MB, zero at load

__device__ __forceinline__ void red_v4p(float* p, float a, float b, float c, float d, int pred) {
    asm volatile(
        "{\n\t"
        ".reg .pred q;\n\t"
        "setp.ne.s32 q, %5, 0;\n\t"
        "@q red.global.add.v4.f32 [%0], {%1, %2, %3, %4};\n\t"
        "}"
        :: "l"(p), "f"(a), "f"(b), "f"(c), "f"(d), "r"(pred) : "memory");
}

__global__ void __launch_bounds__(256) cic_deposit_kernel(
    const float* __restrict__ pos,
    const float* __restrict__ wgt,
    int n)
{
    int i    = blockIdx.x * blockDim.x + threadIdx.x;   // one particle per thread
    int lane = threadIdx.x & 31;
    int h    = lane & 1;          // x-half this lane serves
    int s    = (lane >> 1) & 1;   // z-block this lane serves

    // ---- own particle -> derived values ----
    float xw0 = 0.f, xw1 = 0.f, oyv = 0.f, ozv = 0.f;
    int P = 0;   // pack: B (21b) | [1=valid|bx|by|bz|lx|ly|lz] << 21

    if (i < n) {
        float px = __ldcs(pos + 3 * (size_t)i + 0);
        float py = __ldcs(pos + 3 * (size_t)i + 1);
        float pz = __ldcs(pos + 3 * (size_t)i + 2);
        float w  = __ldcs(wgt + i);

        // Match JAX float32 arithmetic: subtract then IEEE divide
        float fx = (px - GMINF) / DXF;
        float fy = (py - GMINF) / DXF;
        float fz = (pz - GMINF) / DXF;

        float ixf = floorf(fx), iyf = floorf(fy), izf = floorf(fz);
        int cx = (int)ixf, cy = (int)iyf, cz = (int)izf;

        if ((unsigned)cx <= 255u && (unsigned)cy <= 255u && (unsigned)cz <= 255u) {
            float ox = fx - ixf;
            oyv = fy - iyf;
            ozv = fz - izf;
            xw0 = w * (1.0f - ox);   // corner weight = ((w*X)*Y)*Z association
            xw1 = w * ox;
            int B = ((cx >> 1) * 128 + (cy >> 1)) * 128 + (cz >> 1);
            int fl = 1 | ((cx & 1) << 1) | ((cy & 1) << 2) | ((cz & 1) << 3)
                       | ((int)(cx < 255) << 4) | ((int)(cy < 255) << 5)
                       | ((int)(cz < 255) << 6);
            P = B | (fl << 21);
        }
    }

    // ---- 4 rounds: group (4g..4g+3) processes member r's particle ----
    #pragma unroll
    for (int r = 0; r < 4; r++) {
        const unsigned FULL = 0xffffffffu;
        float XW0 = __shfl_sync(FULL, xw0, r, 4);
        float XW1 = __shfl_sync(FULL, xw1, r, 4);
        float OY  = __shfl_sync(FULL, oyv, r, 4);
        float OZ  = __shfl_sync(FULL, ozv, r, 4);
        int   Pp  = __shfl_sync(FULL, P,   r, 4);

        int Bb  = Pp & 0x1FFFFF;
        int F   = ((unsigned)Pp) >> 21;
        int val = F & 1;
        int bx = (F >> 1) & 1, by = (F >> 2) & 1, bz = (F >> 3) & 1;
        int lx = (F >> 4) & 1, ly = (F >> 5) & 1, lz = (F >> 6) & 1;

        float wy0 = 1.0f - OY, wy1 = OY;
        float wz0 = 1.0f - OZ, wz1 = OZ;

        // z values for this lane's z-block (quad lane order: ybit*2 + zbit)
        float zv0 = s ? wz1 : (bz ? 0.0f : wz0);
        float zv1 = s ? 0.0f : (bz ? wz0 : wz1);
        float xw  = h ? XW1 : XW0;

        // y-main (block Y) lane weights per ybit
        float yA0 = by ? 0.0f : wy0;
        float yA1 = by ? wy0  : wy1;

        // lane address: h=0 -> xbit=bx in block X; h=1 -> bx ? block X+1 : +4
        int xoff = h ? (bx ? 131072 : 4) : (bx << 2);   // floats; 131072 = 128*128*8
        float* Q = g_scratch + ((size_t)(unsigned)Bb << 3) + (size_t)(xoff + (s << 3));

        int pA = val & (h ? (bx ? lx : 1) : 1) & (s ? (bz & lz) : 1);
        red_v4p(Q, xw * (yA0 * zv0), xw * (yA0 * zv1),
                   xw * (yA1 * zv0), xw * (yA1 * zv1), pA);

        // y-spill (block Y+1, ybit0 = corner cy+1)
        int pB = pA & by & ly;
        red_v4p(Q + 1024, xw * (wy1 * zv0), xw * (wy1 * zv1), 0.0f, 0.0f, pB);
    }
}

// Fused depermute + rezero via SMEM transpose.
// CTA tile: fixed X, 4 consecutive y-blocks (Yb0..Yb0+3), all 128 z-blocks
// = contiguous 4096 floats (16KB) of scratch.
// Phase 1: coalesced float4 load + coalesced float4 zero-store (restores the
//          scratch-zero invariant), depermuted float2 stores into SMEM.
// Phase 2: coalesced float4 SMEM reads -> coalesced float4 stores to d_out.
__global__ void __launch_bounds__(256) depermute_kernel(float4* __restrict__ out) {
    __shared__ float sm[2 * 8 * 256];    // [x'][yy][z], 16KB

    int X   = blockIdx.x >> 5;           // 0..127
    int Yg  = blockIdx.x & 31;           // y-block group
    int Yb0 = Yg << 2;                   // first of 4 y-blocks
    int tid = threadIdx.x;

    // tile base in float4 units: ((X*128 + Yb0)*128)*8 floats / 4
    size_t base4 = ((size_t)(X * 128 + Yb0) * 128) * 2;
    float4* gs4 = (float4*)g_scratch;

    #pragma unroll
    for (int it = 0; it < 4; it++) {
        int idx = tid + it * 256;        // 0..1023 float4 within tile
        float4 v = gs4[base4 + idx];
        gs4[base4 + idx] = make_float4(0.f, 0.f, 0.f, 0.f);

        int h  = idx & 1;                // x-half
        int b  = idx >> 1;               // block within tile
        int j  = b >> 7;                 // y-block 0..3
        int Zb = b & 127;
        // v = (y0z0, y0z1, y1z0, y1z1) for xbit=h
        float* s0 = sm + ((h << 3) + (j << 1)) * 256 + (Zb << 1);
        s0[0]   = v.x;  s0[1]   = v.y;        // ybit 0
        s0[256] = v.z;  s0[257] = v.w;        // ybit 1
    }
    __syncthreads();

    // output: x in {2X, 2X+1}, y in [2Yb0, 2Yb0+8), z 0..255
    #pragma unroll
    for (int it = 0; it < 4; it++) {
        int o  = tid + it * 256;         // 0..1023
        int z4 = o & 63;
        int yy = (o >> 6) & 7;
        int xb = o >> 9;                 // x'
        float4 v = *(const float4*)(sm + ((xb << 3) + yy) * 256 + (z4 << 2));
        size_t oidx = (((size_t)(2 * X + xb) * 256) + (size_t)(2 * Yb0 + yy)) * 64 + (size_t)z4;
        out[oidx] = v;
    }
}

extern "C" void kernel_launch(void* const* d_in, const int* in_sizes, int n_in,
                              void* d_out, int out_size) {
    const float* positions = (const float*)d_in[0];
    const float* weights   = (const float*)d_in[1];
    float* grid = (float*)d_out;

    int n_particles = in_sizes[1];  // weights element count = N

    // scratch is zero at entry: zero-initialized at module load, re-zeroed by
    // depermute_kernel (coalesced full-line stores) on every prior execution.

    // 1) 4-lane-group deposit: one particle per thread
    int threads = 256;
    int blocks = (n_particles + threads - 1) / threads;
    cic_deposit_kernel<<<blocks, threads>>>(positions, weights, n_particles);

    // 2) fused depermute + rezero -> d_out (fully overwritten)
    depermute_kernel<<<128 * 32, 256>>>((float4*)grid);
}

// round 17
// speedup vs baseline: 1.2111x; 1.2111x over previous
#include <cuda_runtime.h>
#include <cstdint>

// CIC deposition: 10M particles -> 256^3 float grid.
// Round 17: R14 deposit (4-lane groups, 2 RED instr/particle, ~3.12 effective
// sector-RMWs/particle) + zero kernel retained (doubles as L2 prefetch of the
// scratch: R16 showed deposit is ~12us slower on cold scratch) + NEW
// SMEM-transpose depermute (coalesced float4 read of contiguous scratch tiles,
// coalesced float4 write of output rows; replaces the 8B-strided gather that
// cost 28us with ~21us of pure bandwidth).

static constexpr float GMINF = -10.0f;
static constexpr float DXF   = (float)(20.0 / 255.0);

static constexpr size_t NBLK = 128u * 128u * 128u;       // 2,097,152 blocks
__device__ __align__(32) float g_scratch[NBLK * 8];      // 64MB

__global__ void zero_scratch_kernel(int n4) {
    int i = blockIdx.x * blockDim.x + threadIdx.x;
    if (i < n4) ((float4*)g_scratch)[i] = make_float4(0.f, 0.f, 0.f, 0.f);
}

__device__ __forceinline__ void red_v4p(float* p, float a, float b, float c, float d, int pred) {
    asm volatile(
        "{\n\t"
        ".reg .pred q;\n\t"
        "setp.ne.s32 q, %5, 0;\n\t"
        "@q red.global.add.v4.f32 [%0], {%1, %2, %3, %4};\n\t"
        "}"
        :: "l"(p), "f"(a), "f"(b), "f"(c), "f"(d), "r"(pred) : "memory");
}

__global__ void __launch_bounds__(256) cic_deposit_kernel(
    const float* __restrict__ pos,
    const float* __restrict__ wgt,
    int n)
{
    int i    = blockIdx.x * blockDim.x + threadIdx.x;   // one particle per thread
    int lane = threadIdx.x & 31;
    int h    = lane & 1;          // x-half this lane serves
    int s    = (lane >> 1) & 1;   // z-block this lane serves

    // ---- own particle -> derived values ----
    float xw0 = 0.f, xw1 = 0.f, oyv = 0.f, ozv = 0.f;
    int P = 0;   // pack: B (21b) | [1=valid|bx|by|bz|lx|ly|lz] << 21

    if (i < n) {
        float px = __ldcs(pos + 3 * (size_t)i + 0);
        float py = __ldcs(pos + 3 * (size_t)i + 1);
        float pz = __ldcs(pos + 3 * (size_t)i + 2);
        float w  = __ldcs(wgt + i);

        // Match JAX float32 arithmetic: subtract then IEEE divide
        float fx = (px - GMINF) / DXF;
        float fy = (py - GMINF) / DXF;
        float fz = (pz - GMINF) / DXF;

        float ixf = floorf(fx), iyf = floorf(fy), izf = floorf(fz);
        int cx = (int)ixf, cy = (int)iyf, cz = (int)izf;

        if ((unsigned)cx <= 255u && (unsigned)cy <= 255u && (unsigned)cz <= 255u) {
            float ox = fx - ixf;
            oyv = fy - iyf;
            ozv = fz - izf;
            xw0 = w * (1.0f - ox);   // corner weight = ((w*X)*Y)*Z association
            xw1 = w * ox;
            int B = ((cx >> 1) * 128 + (cy >> 1)) * 128 + (cz >> 1);
            int fl = 1 | ((cx & 1) << 1) | ((cy & 1) << 2) | ((cz & 1) << 3)
                       | ((int)(cx < 255) << 4) | ((int)(cy < 255) << 5)
                       | ((int)(cz < 255) << 6);
            P = B | (fl << 21);
        }
    }

    // ---- 4 rounds: group (4g..4g+3) processes member r's particle ----
    #pragma unroll
    for (int r = 0; r < 4; r++) {
        const unsigned FULL = 0xffffffffu;
        float XW0 = __shfl_sync(FULL, xw0, r, 4);
        float XW1 = __shfl_sync(FULL, xw1, r, 4);
        float OY  = __shfl_sync(FULL, oyv, r, 4);
        float OZ  = __shfl_sync(FULL, ozv, r, 4);
        int   Pp  = __shfl_sync(FULL, P,   r, 4);

        int Bb  = Pp & 0x1FFFFF;
        int F   = ((unsigned)Pp) >> 21;
        int val = F & 1;
        int bx = (F >> 1) & 1, by = (F >> 2) & 1, bz = (F >> 3) & 1;
        int lx = (F >> 4) & 1, ly = (F >> 5) & 1, lz = (F >> 6) & 1;

        float wy0 = 1.0f - OY, wy1 = OY;
        float wz0 = 1.0f - OZ, wz1 = OZ;

        // z values for this lane's z-block (quad lane order: ybit*2 + zbit)
        float zv0 = s ? wz1 : (bz ? 0.0f : wz0);
        float zv1 = s ? 0.0f : (bz ? wz0 : wz1);
        float xw  = h ? XW1 : XW0;

        // y-main (block Y) lane weights per ybit
        float yA0 = by ? 0.0f : wy0;
        float yA1 = by ? wy0  : wy1;

        // lane address: h=0 -> xbit=bx in block X; h=1 -> bx ? block X+1 : +4
        int xoff = h ? (bx ? 131072 : 4) : (bx << 2);   // floats; 131072 = 128*128*8
        float* Q = g_scratch + ((size_t)(unsigned)Bb << 3) + (size_t)(xoff + (s << 3));

        int pA = val & (h ? (bx ? lx : 1) : 1) & (s ? (bz & lz) : 1);
        red_v4p(Q, xw * (yA0 * zv0), xw * (yA0 * zv1),
                   xw * (yA1 * zv0), xw * (yA1 * zv1), pA);

        // y-spill (block Y+1, ybit0 = corner cy+1)
        int pB = pA & by & ly;
        red_v4p(Q + 1024, xw * (wy1 * zv0), xw * (wy1 * zv1), 0.0f, 0.0f, pB);
    }
}

// SMEM-transpose depermute (no rezero).
// CTA tile: fixed X, 4 consecutive y-blocks, all 128 z-blocks = contiguous
// 16KB of scratch. Phase 1: coalesced float4 loads, depermuted float2 SMEM
// stores. Phase 2: coalesced float4 SMEM reads -> coalesced float4 stores.
__global__ void __launch_bounds__(256) depermute_kernel(float4* __restrict__ out) {
    __shared__ float sm[2 * 8 * 256];    // [x'][yy][z], 16KB

    int X   = blockIdx.x >> 5;           // 0..127
    int Yg  = blockIdx.x & 31;           // y-block group
    int Yb0 = Yg << 2;                   // first of 4 y-blocks
    int tid = threadIdx.x;

    size_t base4 = ((size_t)(X * 128 + Yb0) * 128) * 2;   // tile base, float4 units
    const float4* gs4 = (const float4*)g_scratch;

    #pragma unroll
    for (int it = 0; it < 4; it++) {
        int idx = tid + it * 256;        // 0..1023 float4 within tile
        float4 v = __ldcs(gs4 + base4 + idx);

        int h  = idx & 1;                // x-half
        int b  = idx >> 1;               // block within tile
        int j  = b >> 7;                 // y-block 0..3
        int Zb = b & 127;
        // v = (y0z0, y0z1, y1z0, y1z1) for xbit=h
        float* s0 = sm + ((h << 3) + (j << 1)) * 256 + (Zb << 1);
        *(float2*)(s0)       = make_float2(v.x, v.y);   // ybit 0
        *(float2*)(s0 + 256) = make_float2(v.z, v.w);   // ybit 1
    }
    __syncthreads();

    // output: x in {2X, 2X+1}, y in [2Yb0, 2Yb0+8), z 0..255
    #pragma unroll
    for (int it = 0; it < 4; it++) {
        int o  = tid + it * 256;         // 0..1023
        int z4 = o & 63;
        int yy = (o >> 6) & 7;
        int xb = o >> 9;                 // x'
        float4 v = *(const float4*)(sm + ((xb << 3) + yy) * 256 + (z4 << 2));
        size_t oidx = (((size_t)(2 * X + xb) * 256) + (size_t)(2 * Yb0 + yy)) * 64 + (size_t)z4;
        out[oidx] = v;
    }
}

extern "C" void kernel_launch(void* const* d_in, const int* in_sizes, int n_in,
                              void* d_out, int out_size) {
    const float* positions = (const float*)d_in[0];
    const float* weights   = (const float*)d_in[1];
    float* grid = (float*)d_out;

    int n_particles = in_sizes[1];  // weights element count = N

    // 1) zero the 64MB permuted scratch (also prefetches it into L2 — R16
    //    showed deposit runs ~12us slower on cold scratch)
    int nz4 = (int)(NBLK * 8 / 4);
    zero_scratch_kernel<<<(nz4 + 255) / 256, 256>>>(nz4);

    // 2) 4-lane-group deposit: one particle per thread
    int threads = 256;
    int blocks = (n_particles + threads - 1) / threads;
    cic_deposit_kernel<<<blocks, threads>>>(positions, weights, n_particles);

    // 3) SMEM-transpose depermute into d_out (fully overwrites it)
    depermute_kernel<<<128 * 32, 256>>>((float4*)grid);
}